// round 6
// baseline (speedup 1.0000x reference)
// bf16 screen (1-pass mma.sync) + exact fp32 rescore — NeighborDiscriminator
#include <cuda_runtime.h>
#include <cuda_bf16.h>
#include <cfloat>
#include <cstdint>

#define D        128
#define MB       128          // queries per block tile
#define NT       128          // x-points per inner tile
#define KSCR     16           // screened per (query, chunk)
#define KSEL     10
#define NSEL     32           // global candidates per query
#define NCHUNK   37           // 16 qtiles * 37 = 592 = 148 * 4
#define GRID_MAIN 148
#define NTHREADS 256
#define MAX_NP   104192       // 37 * 22 * 128
#define MAX_M    2048

// smem layout (bytes)
#define ROWPITCH 272                        // 136 bf16 per row (128 data + pad)
#define SQ_OFF   0                          // 128 rows * 272
#define SX_OFF   (128 * ROWPITCH)           // 34816
#define SX_SLOT  (128 * ROWPITCH)           // 34816 per slot, 2 slots
#define SS_OFF   (SX_OFF + 2 * SX_SLOT)     // 104448
#define SS_PITCH 129
#define SX2_OFF  (SS_OFF + MB * SS_PITCH * 4)   // 170496
#define SMEM_TOTAL (SX2_OFF + 2 * NT * 4)       // 171520

__device__ float g_x2a[MAX_NP];              // ||x||^2 - w  (ranking-equivalent)
__device__ uint4 g_xh[MAX_NP * 16];          // X hi bf16, row = 16 x uint4 (256B)
__device__ uint4 g_qh[MAX_M * 16];           // Q hi bf16
__device__ float g_cand_r[MAX_M * NCHUNK * KSCR];
__device__ int   g_cand_j[MAX_M * NCHUNK * KSCR];
__device__ int   g_sel[MAX_M * NSEL];

// ---------------------------------------------------------------- helpers
__device__ __forceinline__ uint32_t smem_u32(const void* p) {
    uint32_t a;
    asm("{ .reg .u64 t; cvta.to.shared.u64 t, %1; cvt.u32.u64 %0, t; }" : "=r"(a) : "l"(p));
    return a;
}
__device__ __forceinline__ void cp_async16(uint32_t dst, const void* src) {
    asm volatile("cp.async.ca.shared.global [%0], [%1], 16;" :: "r"(dst), "l"(src));
}
#define CP_COMMIT() asm volatile("cp.async.commit_group;" ::: "memory")
#define CP_WAIT0()  asm volatile("cp.async.wait_group 0;" ::: "memory")

__device__ __forceinline__ void ldm_x4(uint32_t& r0, uint32_t& r1, uint32_t& r2, uint32_t& r3,
                                       uint32_t addr) {
    asm volatile("ldmatrix.sync.aligned.m8n8.x4.shared.b16 {%0,%1,%2,%3}, [%4];"
                 : "=r"(r0), "=r"(r1), "=r"(r2), "=r"(r3) : "r"(addr));
}
__device__ __forceinline__ void mma_bf16(float* c, const uint32_t* a, const uint32_t* b) {
    asm volatile("mma.sync.aligned.m16n8k16.row.col.f32.bf16.bf16.f32 "
                 "{%0,%1,%2,%3}, {%4,%5,%6,%7}, {%8,%9}, {%0,%1,%2,%3};"
                 : "+f"(c[0]), "+f"(c[1]), "+f"(c[2]), "+f"(c[3])
                 : "r"(a[0]), "r"(a[1]), "r"(a[2]), "r"(a[3]), "r"(b[0]), "r"(b[1]));
}

template <int KK>
__device__ __forceinline__ void topk_insert(float r, int j, float* br, int* bj) {
#pragma unroll
    for (int t = 0; t < KK; t++) {
        if (r < br[t]) {
            float tr = br[t]; int tj = bj[t];
            br[t] = r; bj[t] = j; r = tr; j = tj;
        }
    }
}

// ---------------------------------------------------------------- prep
__global__ void k_prepx(const float* __restrict__ X, const float* __restrict__ w,
                        int n, int n_pad) {
    int j = blockIdx.x * blockDim.x + threadIdx.x;
    if (j >= n_pad) return;
    if (j >= n) {
        uint4 z = make_uint4(0, 0, 0, 0);
#pragma unroll
        for (int g = 0; g < 16; g++) g_xh[(size_t)j * 16 + g] = z;
        g_x2a[j] = 1e30f;
        return;
    }
    const float4* row = (const float4*)(X + (size_t)j * D);
    float x2 = 0.f;
#pragma unroll
    for (int g = 0; g < 16; g++) {
        float4 f0 = row[2 * g], f1 = row[2 * g + 1];
        x2 += f0.x * f0.x + f0.y * f0.y + f0.z * f0.z + f0.w * f0.w;
        x2 += f1.x * f1.x + f1.y * f1.y + f1.z * f1.z + f1.w * f1.w;
        __nv_bfloat162 h0 = __floats2bfloat162_rn(f0.x, f0.y);
        __nv_bfloat162 h1 = __floats2bfloat162_rn(f0.z, f0.w);
        __nv_bfloat162 h2 = __floats2bfloat162_rn(f1.x, f1.y);
        __nv_bfloat162 h3 = __floats2bfloat162_rn(f1.z, f1.w);
        uint4 h;
        h.x = *reinterpret_cast<uint32_t*>(&h0);
        h.y = *reinterpret_cast<uint32_t*>(&h1);
        h.z = *reinterpret_cast<uint32_t*>(&h2);
        h.w = *reinterpret_cast<uint32_t*>(&h3);
        g_xh[(size_t)j * 16 + g] = h;
    }
    g_x2a[j] = x2 - w[j];   // wmax dropped: constant offset, ranking-invariant
}

__global__ void k_prepq(const float* __restrict__ Xt, int m) {
    int i = blockIdx.x * blockDim.x + threadIdx.x;
    if (i >= m) return;
    const float4* row = (const float4*)(Xt + (size_t)i * D);
#pragma unroll
    for (int g = 0; g < 16; g++) {
        float4 f0 = row[2 * g], f1 = row[2 * g + 1];
        __nv_bfloat162 h0 = __floats2bfloat162_rn(f0.x, f0.y);
        __nv_bfloat162 h1 = __floats2bfloat162_rn(f0.z, f0.w);
        __nv_bfloat162 h2 = __floats2bfloat162_rn(f1.x, f1.y);
        __nv_bfloat162 h3 = __floats2bfloat162_rn(f1.z, f1.w);
        uint4 h;
        h.x = *reinterpret_cast<uint32_t*>(&h0);
        h.y = *reinterpret_cast<uint32_t*>(&h1);
        h.z = *reinterpret_cast<uint32_t*>(&h2);
        h.w = *reinterpret_cast<uint32_t*>(&h3);
        g_qh[(size_t)i * 16 + g] = h;
    }
}

// ---------------------------------------------------------------- main screen
__device__ __forceinline__ void load_x(uint32_t sbase, int slot, int jt, int tid) {
#pragma unroll
    for (int e = tid; e < 2048; e += NTHREADS) {       // 8 iters: 128 rows x 16 u4
        int r = e >> 4, c = e & 15;
        cp_async16(sbase + SX_OFF + slot * SX_SLOT + r * ROWPITCH + c * 16,
                   g_xh + ((size_t)(jt + r) * 16 + c));
    }
    if (tid < 32)
        cp_async16(sbase + SX2_OFF + slot * 512 + tid * 16, g_x2a + jt + tid * 4);
}

__global__ void __launch_bounds__(NTHREADS, 1)
k_main(int n, int n_items, int chunksz) {
    extern __shared__ char smem[];
    float* sS  = (float*)(smem + SS_OFF);
    float* sx2 = (float*)(smem + SX2_OFF);
    const uint32_t sbase = smem_u32(smem);
    const int tid = threadIdx.x;
    const int lane = tid & 31;
    const int wid = tid >> 5;
    const int wm = wid >> 1;     // rows wm*32
    const int wn = wid & 1;      // cols wn*64

    const int a_row  = (lane & 15);
    const int a_colb = ((lane >> 4) * 8) * 2;
    const int b_row  = ((lane >> 4) << 3) + (lane & 7);
    const int b_colb = (((lane >> 3) & 1) * 8) * 2;

    const int tiles_full = chunksz / NT;

    for (int it = blockIdx.x; it < n_items; it += gridDim.x) {
        const int qtile = it / NCHUNK;
        const int chunk = it - qtile * NCHUNK;
        const int j0 = chunk * chunksz;
        int T = tiles_full;
        {
            int rem = n - j0;
            int tr = (rem > 0) ? (rem + NT - 1) / NT : 0;
            if (tr < T) T = tr;
        }

        float br[KSCR]; int bj[KSCR];
#pragma unroll
        for (int t = 0; t < KSCR; t++) { br[t] = FLT_MAX; bj[t] = -1; }

        if (T > 0) {
            // Q hi tile: 128 rows x 16 u4
#pragma unroll
            for (int e = tid; e < 2048; e += NTHREADS) {
                int r = e >> 4, c = e & 15;
                cp_async16(sbase + SQ_OFF + r * ROWPITCH + c * 16,
                           g_qh + ((size_t)(qtile * MB + r) * 16 + c));
            }
            CP_COMMIT();
            load_x(sbase, 0, j0, tid);
            CP_COMMIT();

            for (int t = 0; t < T; t++) {
                const int cur = t & 1;
                CP_WAIT0();
                __syncthreads();
                if (t + 1 < T) { load_x(sbase, 1 - cur, j0 + (t + 1) * NT, tid); CP_COMMIT(); }

                float acc[2][8][4];
#pragma unroll
                for (int mf = 0; mf < 2; mf++)
#pragma unroll
                    for (int nf = 0; nf < 8; nf++)
#pragma unroll
                        for (int e = 0; e < 4; e++) acc[mf][nf][e] = 0.f;

                const uint32_t abase0 = sbase + SQ_OFF + (wm * 32 + a_row) * ROWPITCH + a_colb;
                const uint32_t bbase0 = sbase + SX_OFF + cur * SX_SLOT
                                      + (wn * 64 + b_row) * ROWPITCH + b_colb;
#pragma unroll
                for (int ks = 0; ks < 8; ks++) {
                    const uint32_t kb = ks * 32;
                    uint32_t a[2][4], b[4][4];
                    ldm_x4(a[0][0], a[0][1], a[0][2], a[0][3], abase0 + kb);
                    ldm_x4(a[1][0], a[1][1], a[1][2], a[1][3], abase0 + 16 * ROWPITCH + kb);
#pragma unroll
                    for (int nf = 0; nf < 4; nf++)
                        ldm_x4(b[nf][0], b[nf][1], b[nf][2], b[nf][3],
                               bbase0 + nf * 16 * ROWPITCH + kb);
#pragma unroll
                    for (int mf = 0; mf < 2; mf++) {
#pragma unroll
                        for (int nf = 0; nf < 4; nf++) {
                            mma_bf16(acc[mf][2 * nf],     a[mf], &b[nf][0]);
                            mma_bf16(acc[mf][2 * nf + 1], a[mf], &b[nf][2]);
                        }
                    }
                }

#pragma unroll
                for (int mf = 0; mf < 2; mf++) {
#pragma unroll
                    for (int nf8 = 0; nf8 < 8; nf8++) {
                        int r = wm * 32 + mf * 16 + (lane >> 2);
                        int c = wn * 64 + nf8 * 8 + (lane & 3) * 2;
                        sS[r * SS_PITCH + c]           = acc[mf][nf8][0];
                        sS[r * SS_PITCH + c + 1]       = acc[mf][nf8][1];
                        sS[(r + 8) * SS_PITCH + c]     = acc[mf][nf8][2];
                        sS[(r + 8) * SS_PITCH + c + 1] = acc[mf][nf8][3];
                    }
                }
                __syncthreads();

                if (tid < MB) {
                    const float* srow = sS + tid * SS_PITCH;
                    const float* x2s = sx2 + cur * NT;
                    const int jb = j0 + t * NT;
                    float thr = br[KSCR - 1];
#pragma unroll 4
                    for (int c = 0; c < NT; c++) {
                        float r = fmaf(-2.0f, srow[c], x2s[c]);
                        if (r < thr) {
                            topk_insert<KSCR>(r, jb + c, br, bj);
                            thr = br[KSCR - 1];
                        }
                    }
                }
            }
        }

        if (tid < MB) {
            const int q = qtile * MB + tid;
            const size_t base = ((size_t)q * NCHUNK + chunk) * KSCR;
#pragma unroll
            for (int t = 0; t < KSCR; t++) {
                g_cand_r[base + t] = br[t];
                g_cand_j[base + t] = bj[t];
            }
        }
        __syncthreads();   // smem safe before next item
    }
}

// ---------------------------------------------------------------- global screen
__global__ void k_screen(int m) {
    int q = blockIdx.x * blockDim.x + threadIdx.x;
    if (q >= m) return;
    float br[NSEL]; int bj[NSEL];
#pragma unroll
    for (int t = 0; t < NSEL; t++) { br[t] = FLT_MAX; bj[t] = -1; }
    const size_t base = (size_t)q * NCHUNK * KSCR;
    float thr = FLT_MAX;
    for (int c = 0; c < NCHUNK * KSCR; c++) {
        float r = g_cand_r[base + c];
        if (r < thr) {
            int j = g_cand_j[base + c];
            if (j < 0) continue;
            topk_insert<NSEL>(r, j, br, bj);
            thr = br[NSEL - 1];
        }
    }
#pragma unroll
    for (int t = 0; t < NSEL; t++) g_sel[q * NSEL + t] = bj[t];
}

// ---------------------------------------------------------------- exact rescore
__global__ void k_rescore(const float* __restrict__ Xt, const float* __restrict__ X,
                          const float* __restrict__ w, float* __restrict__ out, int m) {
    __shared__ float sq[8][D];
    const int lane = threadIdx.x & 31;
    const int wgrp = threadIdx.x >> 5;
    const int q = blockIdx.x * 8 + wgrp;
    if (q >= m) return;

    // stage query row
#pragma unroll
    for (int e = lane; e < D; e += 32) sq[wgrp][e] = Xt[(size_t)q * D + e];
    __syncwarp();

    const int j = g_sel[q * NSEL + lane];
    float d2 = 0.f, act = -FLT_MAX, s = FLT_MAX;
    if (j >= 0) {
        const float4* xr = (const float4*)(X + (size_t)j * D);
        const float4* qr = (const float4*)(sq[wgrp]);
#pragma unroll
        for (int v = 0; v < 32; v++) {
            float4 x = xr[v], qq = qr[v];
            float dx = x.x - qq.x, dy = x.y - qq.y, dz = x.z - qq.z, dw = x.w - qq.w;
            d2 += dx * dx + dy * dy + dz * dz + dw * dw;
        }
        float wj = w[j];
        s = d2 - wj;                       // augmented ranking key (wmax dropped)
        act = wj - sqrtf(d2);              // K_CONST = 1
    }
    // rank of this lane's candidate among the 32 (ties -> lower lane wins)
    int rank = 0;
#pragma unroll
    for (int k = 0; k < 32; k++) {
        float sk = __shfl_sync(0xffffffffu, s, k);
        rank += (sk < s) || (sk == s && k < lane);
    }
    float v = (rank < KSEL && j >= 0) ? act : -FLT_MAX;
#pragma unroll
    for (int o = 16; o > 0; o >>= 1)
        v = fmaxf(v, __shfl_xor_sync(0xffffffffu, v, o));
    if (lane == 0) out[q] = v;
}

// ---------------------------------------------------------------- launch
extern "C" void kernel_launch(void* const* d_in, const int* in_sizes, int n_in,
                              void* d_out, int out_size) {
    const float* Xt = (const float*)d_in[0];   // (m, 128)
    const float* X  = (const float*)d_in[1];   // (n, 128)
    const float* w  = (const float*)d_in[2];   // (n,)

    const int m = in_sizes[0] / D;
    const int n = in_sizes[2];

    const int tiles_per_chunk = (n + NCHUNK * NT - 1) / (NCHUNK * NT);   // 22
    const int chunksz = tiles_per_chunk * NT;                            // 2816
    const int n_pad = NCHUNK * chunksz;                                  // 104192
    const int n_items = (m / MB) * NCHUNK;                               // 592

    cudaFuncSetAttribute(k_main, cudaFuncAttributeMaxDynamicSharedMemorySize, SMEM_TOTAL);

    k_prepx<<<(n_pad + 255) / 256, 256>>>(X, w, n, n_pad);
    k_prepq<<<(m + 127) / 128, 128>>>(Xt, m);
    k_main<<<GRID_MAIN, NTHREADS, SMEM_TOTAL>>>(n, n_items, chunksz);
    k_screen<<<(m + 127) / 128, 128>>>(m);
    k_rescore<<<(m + 7) / 8, 256>>>(Xt, X, w, (float*)d_out, m);
}

// round 7
// speedup vs baseline: 1.3177x; 1.3177x over previous
// bf16 screen (1-pass mma.sync, 512thr) + warp-select + exact fp32 rescore
#include <cuda_runtime.h>
#include <cuda_bf16.h>
#include <cfloat>
#include <cstdint>

#define D        128
#define MB       128          // queries per block tile
#define NT       128          // x-points per inner tile
#define KSCR     12           // screened per (query, chunk)
#define KSEL     10
#define NCHUNK   37           // 16 qtiles * 37 = 592 = 148 * 4
#define GRID_MAIN 148
#define NTHREADS 512
#define MAX_NP   104192       // 37 * 22 * 128
#define MAX_M    2048
#define NCAND    (NCHUNK * KSCR)   // 444

// smem layout (bytes)
#define ROWPITCH 272                        // 136 bf16 per row (128 data + pad)
#define SQ_OFF   0                          // 128 rows * 272
#define SX_OFF   (128 * ROWPITCH)           // 34816
#define SX_SLOT  (128 * ROWPITCH)           // 34816 per slot, 2 slots
#define SS_OFF   (SX_OFF + 2 * SX_SLOT)     // 104448
#define SS_PITCH 129
#define SX2_OFF  (SS_OFF + MB * SS_PITCH * 4)   // 170496
#define SMEM_TOTAL (SX2_OFF + 2 * NT * 4)       // 171520

__device__ float g_x2a[MAX_NP];              // ||x||^2 - w  (ranking-equivalent)
__device__ uint4 g_xh[MAX_NP * 16];          // X hi bf16, row = 16 x uint4 (256B)
__device__ uint4 g_qh[MAX_M * 16];           // Q hi bf16
__device__ float g_cand_r[MAX_M * NCAND];
__device__ int   g_cand_j[MAX_M * NCAND];
__device__ int   g_dummy;

// ---------------------------------------------------------------- helpers
__device__ __forceinline__ uint32_t smem_u32(const void* p) {
    uint32_t a;
    asm("{ .reg .u64 t; cvta.to.shared.u64 t, %1; cvt.u32.u64 %0, t; }" : "=r"(a) : "l"(p));
    return a;
}
__device__ __forceinline__ void cp_async16(uint32_t dst, const void* src) {
    asm volatile("cp.async.ca.shared.global [%0], [%1], 16;" :: "r"(dst), "l"(src));
}
#define CP_COMMIT() asm volatile("cp.async.commit_group;" ::: "memory")
#define CP_WAIT0()  asm volatile("cp.async.wait_group 0;" ::: "memory")

__device__ __forceinline__ void ldm_x4(uint32_t& r0, uint32_t& r1, uint32_t& r2, uint32_t& r3,
                                       uint32_t addr) {
    asm volatile("ldmatrix.sync.aligned.m8n8.x4.shared.b16 {%0,%1,%2,%3}, [%4];"
                 : "=r"(r0), "=r"(r1), "=r"(r2), "=r"(r3) : "r"(addr));
}
__device__ __forceinline__ void mma_bf16(float* c, const uint32_t* a, const uint32_t* b) {
    asm volatile("mma.sync.aligned.m16n8k16.row.col.f32.bf16.bf16.f32 "
                 "{%0,%1,%2,%3}, {%4,%5,%6,%7}, {%8,%9}, {%0,%1,%2,%3};"
                 : "+f"(c[0]), "+f"(c[1]), "+f"(c[2]), "+f"(c[3])
                 : "r"(a[0]), "r"(a[1]), "r"(a[2]), "r"(a[3]), "r"(b[0]), "r"(b[1]));
}

template <int KK>
__device__ __forceinline__ void topk_insert(float r, int j, float* br, int* bj) {
#pragma unroll
    for (int t = 0; t < KK; t++) {
        if (r < br[t]) {
            float tr = br[t]; int tj = bj[t];
            br[t] = r; bj[t] = j; r = tr; j = tj;
        }
    }
}

// ---------------------------------------------------------------- prep
__global__ void k_prepx(const float* __restrict__ X, const float* __restrict__ w,
                        int n, int n_pad) {
    int j = blockIdx.x * blockDim.x + threadIdx.x;
    if (j >= n_pad) return;
    if (j >= n) {
        uint4 z = make_uint4(0, 0, 0, 0);
#pragma unroll
        for (int g = 0; g < 16; g++) g_xh[(size_t)j * 16 + g] = z;
        g_x2a[j] = 1e30f;
        return;
    }
    const float4* row = (const float4*)(X + (size_t)j * D);
    float x2 = 0.f;
#pragma unroll
    for (int g = 0; g < 16; g++) {
        float4 f0 = row[2 * g], f1 = row[2 * g + 1];
        x2 += f0.x * f0.x + f0.y * f0.y + f0.z * f0.z + f0.w * f0.w;
        x2 += f1.x * f1.x + f1.y * f1.y + f1.z * f1.z + f1.w * f1.w;
        __nv_bfloat162 h0 = __floats2bfloat162_rn(f0.x, f0.y);
        __nv_bfloat162 h1 = __floats2bfloat162_rn(f0.z, f0.w);
        __nv_bfloat162 h2 = __floats2bfloat162_rn(f1.x, f1.y);
        __nv_bfloat162 h3 = __floats2bfloat162_rn(f1.z, f1.w);
        uint4 h;
        h.x = *reinterpret_cast<uint32_t*>(&h0);
        h.y = *reinterpret_cast<uint32_t*>(&h1);
        h.z = *reinterpret_cast<uint32_t*>(&h2);
        h.w = *reinterpret_cast<uint32_t*>(&h3);
        g_xh[(size_t)j * 16 + g] = h;
    }
    g_x2a[j] = x2 - w[j];   // additive wmax const dropped: ranking-invariant
}

__global__ void k_prepq(const float* __restrict__ Xt, int m) {
    int i = blockIdx.x * blockDim.x + threadIdx.x;
    if (i >= m) return;
    const float4* row = (const float4*)(Xt + (size_t)i * D);
#pragma unroll
    for (int g = 0; g < 16; g++) {
        float4 f0 = row[2 * g], f1 = row[2 * g + 1];
        __nv_bfloat162 h0 = __floats2bfloat162_rn(f0.x, f0.y);
        __nv_bfloat162 h1 = __floats2bfloat162_rn(f0.z, f0.w);
        __nv_bfloat162 h2 = __floats2bfloat162_rn(f1.x, f1.y);
        __nv_bfloat162 h3 = __floats2bfloat162_rn(f1.z, f1.w);
        uint4 h;
        h.x = *reinterpret_cast<uint32_t*>(&h0);
        h.y = *reinterpret_cast<uint32_t*>(&h1);
        h.z = *reinterpret_cast<uint32_t*>(&h2);
        h.w = *reinterpret_cast<uint32_t*>(&h3);
        g_qh[(size_t)i * 16 + g] = h;
    }
}

__global__ void k_dummy() { if (threadIdx.x == 0) g_dummy = 1; }

// ---------------------------------------------------------------- main screen
__device__ __forceinline__ void load_x(uint32_t sbase, int slot, int jt, int tid) {
#pragma unroll
    for (int e = tid; e < 2048; e += NTHREADS) {       // 4 iters: 128 rows x 16 u4
        int r = e >> 4, c = e & 15;
        cp_async16(sbase + SX_OFF + slot * SX_SLOT + r * ROWPITCH + c * 16,
                   g_xh + ((size_t)(jt + r) * 16 + c));
    }
    if (tid < 32)
        cp_async16(sbase + SX2_OFF + slot * 512 + tid * 16, g_x2a + jt + tid * 4);
}

__global__ void __launch_bounds__(NTHREADS, 1)
k_main(int n, int n_items, int chunksz) {
    extern __shared__ char smem[];
    float* sS  = (float*)(smem + SS_OFF);
    float* sx2 = (float*)(smem + SX2_OFF);
    const uint32_t sbase = smem_u32(smem);
    const int tid = threadIdx.x;
    const int lane = tid & 31;
    const int wid = tid >> 5;
    const int wm = wid >> 1;     // 0..7 -> 16-row strip
    const int wn = wid & 1;      // 0..1 -> 64-col half

    const int a_row  = (lane & 15);
    const int a_colb = ((lane >> 4) * 8) * 2;
    const int b_row  = ((lane >> 4) << 3) + (lane & 7);
    const int b_colb = (((lane >> 3) & 1) * 8) * 2;

    const int tiles_full = chunksz / NT;

    for (int it = blockIdx.x; it < n_items; it += gridDim.x) {
        const int qtile = it / NCHUNK;
        const int chunk = it - qtile * NCHUNK;
        const int j0 = chunk * chunksz;
        int T = tiles_full;
        {
            int rem = n - j0;
            int tr = (rem > 0) ? (rem + NT - 1) / NT : 0;
            if (tr < T) T = tr;
        }

        float br[KSCR]; int bj[KSCR];
#pragma unroll
        for (int t = 0; t < KSCR; t++) { br[t] = FLT_MAX; bj[t] = -1; }

        if (T > 0) {
            // Q hi tile: 128 rows x 16 u4
#pragma unroll
            for (int e = tid; e < 2048; e += NTHREADS) {
                int r = e >> 4, c = e & 15;
                cp_async16(sbase + SQ_OFF + r * ROWPITCH + c * 16,
                           g_qh + ((size_t)(qtile * MB + r) * 16 + c));
            }
            CP_COMMIT();
            load_x(sbase, 0, j0, tid);
            CP_COMMIT();

            for (int t = 0; t < T; t++) {
                const int cur = t & 1;
                CP_WAIT0();
                __syncthreads();
                if (t + 1 < T) { load_x(sbase, 1 - cur, j0 + (t + 1) * NT, tid); CP_COMMIT(); }

                float acc[8][4];
#pragma unroll
                for (int nf = 0; nf < 8; nf++)
#pragma unroll
                    for (int e = 0; e < 4; e++) acc[nf][e] = 0.f;

                const uint32_t abase0 = sbase + SQ_OFF + (wm * 16 + a_row) * ROWPITCH + a_colb;
                const uint32_t bbase0 = sbase + SX_OFF + cur * SX_SLOT
                                      + (wn * 64 + b_row) * ROWPITCH + b_colb;
#pragma unroll
                for (int ks = 0; ks < 8; ks++) {
                    const uint32_t kb = ks * 32;
                    uint32_t a[4], b[4][4];
                    ldm_x4(a[0], a[1], a[2], a[3], abase0 + kb);
#pragma unroll
                    for (int nf = 0; nf < 4; nf++)
                        ldm_x4(b[nf][0], b[nf][1], b[nf][2], b[nf][3],
                               bbase0 + nf * 16 * ROWPITCH + kb);
#pragma unroll
                    for (int nf = 0; nf < 4; nf++) {
                        mma_bf16(acc[2 * nf],     a, &b[nf][0]);
                        mma_bf16(acc[2 * nf + 1], a, &b[nf][2]);
                    }
                }

#pragma unroll
                for (int nf8 = 0; nf8 < 8; nf8++) {
                    int r = wm * 16 + (lane >> 2);
                    int c = wn * 64 + nf8 * 8 + (lane & 3) * 2;
                    sS[r * SS_PITCH + c]           = acc[nf8][0];
                    sS[r * SS_PITCH + c + 1]       = acc[nf8][1];
                    sS[(r + 8) * SS_PITCH + c]     = acc[nf8][2];
                    sS[(r + 8) * SS_PITCH + c + 1] = acc[nf8][3];
                }
                __syncthreads();

                if (tid < MB) {
                    const float* srow = sS + tid * SS_PITCH;
                    const float* x2s = sx2 + cur * NT;
                    const int jb = j0 + t * NT;
                    float thr = br[KSCR - 1];
#pragma unroll 4
                    for (int c = 0; c < NT; c++) {
                        float r = fmaf(-2.0f, srow[c], x2s[c]);
                        if (r < thr) {
                            topk_insert<KSCR>(r, jb + c, br, bj);
                            thr = br[KSCR - 1];
                        }
                    }
                }
            }
        }

        if (tid < MB) {
            const int q = qtile * MB + tid;
            const size_t base = (size_t)q * NCAND + chunk * KSCR;
#pragma unroll
            for (int t = 0; t < KSCR; t++) {
                g_cand_r[base + t] = br[t];
                g_cand_j[base + t] = bj[t];
            }
        }
        __syncthreads();   // smem safe before next item
    }
}

// ------------------------------------------- warp-per-query select + rescore
__global__ void k_select(const float* __restrict__ Xt, const float* __restrict__ X,
                         const float* __restrict__ w, float* __restrict__ out, int m) {
    __shared__ float sq[8][D];
    const int lane = threadIdx.x & 31;
    const int wgrp = threadIdx.x >> 5;
    const int q = blockIdx.x * 8 + wgrp;
    if (q >= m) return;

    // stage the query row
#pragma unroll
    for (int e = lane; e < D; e += 32) sq[wgrp][e] = Xt[(size_t)q * D + e];
    __syncwarp();

    // per-lane top-8 over this query's candidate list (stride-32, coalesced)
    float lr[8]; int lj[8];
#pragma unroll
    for (int t = 0; t < 8; t++) { lr[t] = FLT_MAX; lj[t] = -1; }
    const size_t base = (size_t)q * NCAND;
    for (int c = lane; c < NCAND; c += 32) {
        float r = g_cand_r[base + c];
        if (r < lr[7] && r < 1e29f) {
            int j = g_cand_j[base + c];
            if (j >= 0) topk_insert<8>(r, j, lr, lj);
        }
    }

    // 32-round warp argmin pop -> exact top-32 of the union; round k goes to lane k
    int myj = -1;
    int p = 0;
    for (int round = 0; round < 32; round++) {
        float v = (p < 8) ? lr[p] : FLT_MAX;
        float bv = v; int bl = lane;
#pragma unroll
        for (int o = 16; o > 0; o >>= 1) {
            float ov = __shfl_xor_sync(0xffffffffu, bv, o);
            int   ol = __shfl_xor_sync(0xffffffffu, bl, o);
            if (ov < bv || (ov == bv && ol < bl)) { bv = ov; bl = ol; }
        }
        int jcur = (p < 8) ? lj[p] : -1;
        int jpop = __shfl_sync(0xffffffffu, jcur, bl);
        if (lane == round && bv < 1e29f) myj = jpop;
        if (lane == bl) p++;
    }

    // exact fp32 rescore of this lane's candidate
    float s = FLT_MAX, act = -FLT_MAX;
    if (myj >= 0) {
        const float4* xr = (const float4*)(X + (size_t)myj * D);
        const float4* qr = (const float4*)(sq[wgrp]);
        float d2 = 0.f;
#pragma unroll
        for (int v = 0; v < 32; v++) {
            float4 x = xr[v], qq = qr[v];
            float dx = x.x - qq.x, dy = x.y - qq.y, dz = x.z - qq.z, dw = x.w - qq.w;
            d2 += dx * dx + dy * dy + dz * dz + dw * dw;
        }
        float wj = w[myj];
        s = d2 - wj;              // exact augmented key (wmax const dropped)
        act = wj - sqrtf(d2);     // K_CONST = 1
    }

    // exact top-10 by s, max act over them (10-round pop)
    float mx = -FLT_MAX;
    for (int round = 0; round < KSEL; round++) {
        float bv = s; int bl = lane;
#pragma unroll
        for (int o = 16; o > 0; o >>= 1) {
            float ov = __shfl_xor_sync(0xffffffffu, bv, o);
            int   ol = __shfl_xor_sync(0xffffffffu, bl, o);
            if (ov < bv || (ov == bv && ol < bl)) { bv = ov; bl = ol; }
        }
        float awin = __shfl_sync(0xffffffffu, act, bl);
        if (bv < FLT_MAX) mx = fmaxf(mx, awin);
        if (lane == bl) s = FLT_MAX;
    }
    if (lane == 0) out[q] = mx;
}

// ---------------------------------------------------------------- launch
extern "C" void kernel_launch(void* const* d_in, const int* in_sizes, int n_in,
                              void* d_out, int out_size) {
    const float* Xt = (const float*)d_in[0];   // (m, 128)
    const float* X  = (const float*)d_in[1];   // (n, 128)
    const float* w  = (const float*)d_in[2];   // (n,)

    const int m = in_sizes[0] / D;
    const int n = in_sizes[2];

    const int tiles_per_chunk = (n + NCHUNK * NT - 1) / (NCHUNK * NT);   // 22
    const int chunksz = tiles_per_chunk * NT;                            // 2816
    const int n_pad = NCHUNK * chunksz;                                  // 104192
    const int n_items = (m / MB) * NCHUNK;                               // 592

    cudaFuncSetAttribute(k_main, cudaFuncAttributeMaxDynamicSharedMemorySize, SMEM_TOTAL);

    k_prepx<<<(n_pad + 255) / 256, 256>>>(X, w, n, n_pad);
    k_prepq<<<(m + 127) / 128, 128>>>(Xt, m);
    k_dummy<<<1, 32>>>();
    k_main<<<GRID_MAIN, NTHREADS, SMEM_TOTAL>>>(n, n_items, chunksz);   // 4th launch -> ncu
    k_select<<<(m + 7) / 8, 256>>>(Xt, X, w, (float*)d_out, m);
}

// round 8
// speedup vs baseline: 3.6800x; 2.7928x over previous
// bf16 screen (register-epilogue mma.sync) + warp-select + exact fp32 rescore
#include <cuda_runtime.h>
#include <cuda_bf16.h>
#include <cfloat>
#include <cstdint>

#define D        128
#define MB       128          // queries per block tile
#define NT       128          // x-points per inner tile
#define KSEL     10
#define NCHUNK   37           // 16 qtiles * 37 = 592 = 148 * 4
#define GRID_MAIN 148
#define NTHREADS 512
#define MAX_NP   104192       // 37 * 22 * 128
#define MAX_M    2048
#define LCELL    3            // top-L per (thread, row) cell
#define KCH      24           // candidates per (query, chunk) = 8 cells * LCELL
#define NCAND    (NCHUNK * KCH)   // 888

// smem layout (bytes)
#define ROWPITCH 272                        // 136 bf16 per row (128 data + pad)
#define SQ_OFF   0                          // 128 rows * 272
#define SX_OFF   (128 * ROWPITCH)           // 34816
#define SX_SLOT  (128 * ROWPITCH)           // 34816 per slot, 2 slots
#define SX2_OFF  (SX_OFF + 2 * SX_SLOT)     // 104448
#define SMEM_TOTAL (SX2_OFF + 2 * NT * 4)   // 105472

__device__ float g_x2a[MAX_NP];              // ||x||^2 - w  (ranking-equivalent)
__device__ uint4 g_xh[MAX_NP * 16];          // X hi bf16, row = 16 x uint4 (256B)
__device__ uint4 g_qh[MAX_M * 16];           // Q hi bf16
__device__ float g_cand_r[MAX_M * NCAND];
__device__ int   g_cand_j[MAX_M * NCAND];
__device__ int   g_dummy;

// ---------------------------------------------------------------- helpers
__device__ __forceinline__ uint32_t smem_u32(const void* p) {
    uint32_t a;
    asm("{ .reg .u64 t; cvta.to.shared.u64 t, %1; cvt.u32.u64 %0, t; }" : "=r"(a) : "l"(p));
    return a;
}
__device__ __forceinline__ void cp_async16(uint32_t dst, const void* src) {
    asm volatile("cp.async.ca.shared.global [%0], [%1], 16;" :: "r"(dst), "l"(src));
}
#define CP_COMMIT() asm volatile("cp.async.commit_group;" ::: "memory")
#define CP_WAIT0()  asm volatile("cp.async.wait_group 0;" ::: "memory")

__device__ __forceinline__ void ldm_x4(uint32_t& r0, uint32_t& r1, uint32_t& r2, uint32_t& r3,
                                       uint32_t addr) {
    asm volatile("ldmatrix.sync.aligned.m8n8.x4.shared.b16 {%0,%1,%2,%3}, [%4];"
                 : "=r"(r0), "=r"(r1), "=r"(r2), "=r"(r3) : "r"(addr));
}
__device__ __forceinline__ void mma_bf16(float* c, const uint32_t* a, const uint32_t* b) {
    asm volatile("mma.sync.aligned.m16n8k16.row.col.f32.bf16.bf16.f32 "
                 "{%0,%1,%2,%3}, {%4,%5,%6,%7}, {%8,%9}, {%0,%1,%2,%3};"
                 : "+f"(c[0]), "+f"(c[1]), "+f"(c[2]), "+f"(c[3])
                 : "r"(a[0]), "r"(a[1]), "r"(a[2]), "r"(a[3]), "r"(b[0]), "r"(b[1]));
}

template <int KK>
__device__ __forceinline__ void topk_insert(float r, int j, float* br, int* bj) {
#pragma unroll
    for (int t = 0; t < KK; t++) {
        if (r < br[t]) {
            float tr = br[t]; int tj = bj[t];
            br[t] = r; bj[t] = j; r = tr; j = tj;
        }
    }
}

// ---------------------------------------------------------------- prep
__global__ void k_prepx(const float* __restrict__ X, const float* __restrict__ w,
                        int n, int n_pad) {
    int j = blockIdx.x * blockDim.x + threadIdx.x;
    if (j >= n_pad) return;
    if (j >= n) {
        uint4 z = make_uint4(0, 0, 0, 0);
#pragma unroll
        for (int g = 0; g < 16; g++) g_xh[(size_t)j * 16 + g] = z;
        g_x2a[j] = 1e30f;
        return;
    }
    const float4* row = (const float4*)(X + (size_t)j * D);
    float x2 = 0.f;
#pragma unroll
    for (int g = 0; g < 16; g++) {
        float4 f0 = row[2 * g], f1 = row[2 * g + 1];
        x2 += f0.x * f0.x + f0.y * f0.y + f0.z * f0.z + f0.w * f0.w;
        x2 += f1.x * f1.x + f1.y * f1.y + f1.z * f1.z + f1.w * f1.w;
        __nv_bfloat162 h0 = __floats2bfloat162_rn(f0.x, f0.y);
        __nv_bfloat162 h1 = __floats2bfloat162_rn(f0.z, f0.w);
        __nv_bfloat162 h2 = __floats2bfloat162_rn(f1.x, f1.y);
        __nv_bfloat162 h3 = __floats2bfloat162_rn(f1.z, f1.w);
        uint4 h;
        h.x = *reinterpret_cast<uint32_t*>(&h0);
        h.y = *reinterpret_cast<uint32_t*>(&h1);
        h.z = *reinterpret_cast<uint32_t*>(&h2);
        h.w = *reinterpret_cast<uint32_t*>(&h3);
        g_xh[(size_t)j * 16 + g] = h;
    }
    g_x2a[j] = x2 - w[j];   // additive wmax const dropped: ranking-invariant
}

__global__ void k_prepq(const float* __restrict__ Xt, int m) {
    int i = blockIdx.x * blockDim.x + threadIdx.x;
    if (i >= m) return;
    const float4* row = (const float4*)(Xt + (size_t)i * D);
#pragma unroll
    for (int g = 0; g < 16; g++) {
        float4 f0 = row[2 * g], f1 = row[2 * g + 1];
        __nv_bfloat162 h0 = __floats2bfloat162_rn(f0.x, f0.y);
        __nv_bfloat162 h1 = __floats2bfloat162_rn(f0.z, f0.w);
        __nv_bfloat162 h2 = __floats2bfloat162_rn(f1.x, f1.y);
        __nv_bfloat162 h3 = __floats2bfloat162_rn(f1.z, f1.w);
        uint4 h;
        h.x = *reinterpret_cast<uint32_t*>(&h0);
        h.y = *reinterpret_cast<uint32_t*>(&h1);
        h.z = *reinterpret_cast<uint32_t*>(&h2);
        h.w = *reinterpret_cast<uint32_t*>(&h3);
        g_qh[(size_t)i * 16 + g] = h;
    }
}

__global__ void k_dummy() { if (threadIdx.x == 0) g_dummy = 1; }

// ---------------------------------------------------------------- main screen
__device__ __forceinline__ void load_x(uint32_t sbase, int slot, int jt, int tid) {
#pragma unroll
    for (int e = tid; e < 2048; e += NTHREADS) {       // 4 iters: 128 rows x 16 u4
        int r = e >> 4, c = e & 15;
        cp_async16(sbase + SX_OFF + slot * SX_SLOT + r * ROWPITCH + c * 16,
                   g_xh + ((size_t)(jt + r) * 16 + c));
    }
    if (tid < 32)
        cp_async16(sbase + SX2_OFF + slot * 512 + tid * 16, g_x2a + jt + tid * 4);
}

__global__ void __launch_bounds__(NTHREADS, 1)
k_main(int n, int n_items, int chunksz) {
    extern __shared__ char smem[];
    float* sx2 = (float*)(smem + SX2_OFF);
    const uint32_t sbase = smem_u32(smem);
    const int tid = threadIdx.x;
    const int lane = tid & 31;
    const int wid = tid >> 5;
    const int wm = wid >> 1;     // 0..7 -> 16-row strip
    const int wn = wid & 1;      // 0..1 -> 64-col half

    const int a_row  = (lane & 15);
    const int a_colb = ((lane >> 4) * 8) * 2;
    const int b_row  = ((lane >> 4) << 3) + (lane & 7);
    const int b_colb = (((lane >> 3) & 1) * 8) * 2;
    const int cbase  = wn * 64 + (lane & 3) * 2;   // this thread's first column

    const int tiles_full = chunksz / NT;

    for (int it = blockIdx.x; it < n_items; it += gridDim.x) {
        const int qtile = it / NCHUNK;
        const int chunk = it - qtile * NCHUNK;
        const int j0 = chunk * chunksz;
        int T = tiles_full;
        {
            int rem = n - j0;
            int tr = (rem > 0) ? (rem + NT - 1) / NT : 0;
            if (tr < T) T = tr;
        }

        // per-thread top-L for its 2 fragment rows
        float br0[LCELL], br1[LCELL]; int bj0[LCELL], bj1[LCELL];
#pragma unroll
        for (int t = 0; t < LCELL; t++) {
            br0[t] = FLT_MAX; bj0[t] = -1;
            br1[t] = FLT_MAX; bj1[t] = -1;
        }

        if (T > 0) {
            // Q hi tile: 128 rows x 16 u4
#pragma unroll
            for (int e = tid; e < 2048; e += NTHREADS) {
                int r = e >> 4, c = e & 15;
                cp_async16(sbase + SQ_OFF + r * ROWPITCH + c * 16,
                           g_qh + ((size_t)(qtile * MB + r) * 16 + c));
            }
            CP_COMMIT();
            load_x(sbase, 0, j0, tid);
            CP_COMMIT();

            for (int t = 0; t < T; t++) {
                const int cur = t & 1;
                CP_WAIT0();
                __syncthreads();
                if (t + 1 < T) { load_x(sbase, 1 - cur, j0 + (t + 1) * NT, tid); CP_COMMIT(); }

                float acc[8][4];
#pragma unroll
                for (int nf = 0; nf < 8; nf++)
#pragma unroll
                    for (int e = 0; e < 4; e++) acc[nf][e] = 0.f;

                const uint32_t abase0 = sbase + SQ_OFF + (wm * 16 + a_row) * ROWPITCH + a_colb;
                const uint32_t bbase0 = sbase + SX_OFF + cur * SX_SLOT
                                      + (wn * 64 + b_row) * ROWPITCH + b_colb;
#pragma unroll
                for (int ks = 0; ks < 8; ks++) {
                    const uint32_t kb = ks * 32;
                    uint32_t a[4], b[4][4];
                    ldm_x4(a[0], a[1], a[2], a[3], abase0 + kb);
#pragma unroll
                    for (int nf = 0; nf < 4; nf++)
                        ldm_x4(b[nf][0], b[nf][1], b[nf][2], b[nf][3],
                               bbase0 + nf * 16 * ROWPITCH + kb);
#pragma unroll
                    for (int nf = 0; nf < 4; nf++) {
                        mma_bf16(acc[2 * nf],     a, &b[nf][0]);
                        mma_bf16(acc[2 * nf + 1], a, &b[nf][2]);
                    }
                }

                // register epilogue: all 512 threads, own fragment values only
                const float* x2s = sx2 + cur * NT;
                const int jb = j0 + t * NT;
                float thr0 = br0[LCELL - 1], thr1 = br1[LCELL - 1];
#pragma unroll
                for (int nf8 = 0; nf8 < 8; nf8++) {
                    const int c = cbase + nf8 * 8;
                    const float x0 = x2s[c], x1 = x2s[c + 1];
                    float r;
                    r = fmaf(-2.0f, acc[nf8][0], x0);
                    if (r < thr0) { topk_insert<LCELL>(r, jb + c,     br0, bj0); thr0 = br0[LCELL - 1]; }
                    r = fmaf(-2.0f, acc[nf8][1], x1);
                    if (r < thr0) { topk_insert<LCELL>(r, jb + c + 1, br0, bj0); thr0 = br0[LCELL - 1]; }
                    r = fmaf(-2.0f, acc[nf8][2], x0);
                    if (r < thr1) { topk_insert<LCELL>(r, jb + c,     br1, bj1); thr1 = br1[LCELL - 1]; }
                    r = fmaf(-2.0f, acc[nf8][3], x1);
                    if (r < thr1) { topk_insert<LCELL>(r, jb + c + 1, br1, bj1); thr1 = br1[LCELL - 1]; }
                }
            }
        }

        // write this thread's cells (rows wm*16+(lane>>2) and +8)
        {
            const int q0 = qtile * MB + wm * 16 + (lane >> 2);
            const int cell = wn * 4 + (lane & 3);      // 0..7
            size_t b0 = (size_t)q0 * NCAND + chunk * KCH + cell * LCELL;
            size_t b1 = (size_t)(q0 + 8) * NCAND + chunk * KCH + cell * LCELL;
#pragma unroll
            for (int t = 0; t < LCELL; t++) {
                g_cand_r[b0 + t] = br0[t];  g_cand_j[b0 + t] = bj0[t];
                g_cand_r[b1 + t] = br1[t];  g_cand_j[b1 + t] = bj1[t];
            }
        }
        __syncthreads();   // smem (sQ/sX/sx2) safe before next item's loads
    }
}

// ------------------------------------------- warp-per-query select + rescore
__global__ void k_select(const float* __restrict__ Xt, const float* __restrict__ X,
                         const float* __restrict__ w, float* __restrict__ out, int m) {
    __shared__ float sq[8][D];
    const int lane = threadIdx.x & 31;
    const int wgrp = threadIdx.x >> 5;
    const int q = blockIdx.x * 8 + wgrp;
    if (q >= m) return;

    // stage the query row
#pragma unroll
    for (int e = lane; e < D; e += 32) sq[wgrp][e] = Xt[(size_t)q * D + e];
    __syncwarp();

    // per-lane top-8 over this query's candidate list (stride-32, coalesced)
    float lr[8]; int lj[8];
#pragma unroll
    for (int t = 0; t < 8; t++) { lr[t] = FLT_MAX; lj[t] = -1; }
    const size_t base = (size_t)q * NCAND;
    for (int c = lane; c < NCAND; c += 32) {
        float r = g_cand_r[base + c];
        if (r < lr[7] && r < 1e29f) {
            int j = g_cand_j[base + c];
            if (j >= 0) topk_insert<8>(r, j, lr, lj);
        }
    }

    // 32-round warp argmin pop -> top-32 of the union; round k goes to lane k
    int myj = -1;
    int p = 0;
    for (int round = 0; round < 32; round++) {
        float v = (p < 8) ? lr[p] : FLT_MAX;
        float bv = v; int bl = lane;
#pragma unroll
        for (int o = 16; o > 0; o >>= 1) {
            float ov = __shfl_xor_sync(0xffffffffu, bv, o);
            int   ol = __shfl_xor_sync(0xffffffffu, bl, o);
            if (ov < bv || (ov == bv && ol < bl)) { bv = ov; bl = ol; }
        }
        int jcur = (p < 8) ? lj[p] : -1;
        int jpop = __shfl_sync(0xffffffffu, jcur, bl);
        if (lane == round && bv < 1e29f) myj = jpop;
        if (lane == bl) p++;
    }

    // exact fp32 rescore of this lane's candidate
    float s = FLT_MAX, act = -FLT_MAX;
    if (myj >= 0) {
        const float4* xr = (const float4*)(X + (size_t)myj * D);
        const float4* qr = (const float4*)(sq[wgrp]);
        float d2 = 0.f;
#pragma unroll
        for (int v = 0; v < 32; v++) {
            float4 x = xr[v], qq = qr[v];
            float dx = x.x - qq.x, dy = x.y - qq.y, dz = x.z - qq.z, dw = x.w - qq.w;
            d2 += dx * dx + dy * dy + dz * dz + dw * dw;
        }
        float wj = w[myj];
        s = d2 - wj;              // exact augmented key (wmax const dropped)
        act = wj - sqrtf(d2);     // K_CONST = 1
    }

    // exact top-10 by s, max act over them (10-round pop)
    float mx = -FLT_MAX;
    for (int round = 0; round < KSEL; round++) {
        float bv = s; int bl = lane;
#pragma unroll
        for (int o = 16; o > 0; o >>= 1) {
            float ov = __shfl_xor_sync(0xffffffffu, bv, o);
            int   ol = __shfl_xor_sync(0xffffffffu, bl, o);
            if (ov < bv || (ov == bv && ol < bl)) { bv = ov; bl = ol; }
        }
        float awin = __shfl_sync(0xffffffffu, act, bl);
        if (bv < FLT_MAX) mx = fmaxf(mx, awin);
        if (lane == bl) s = FLT_MAX;
    }
    if (lane == 0) out[q] = mx;
}

// ---------------------------------------------------------------- launch
extern "C" void kernel_launch(void* const* d_in, const int* in_sizes, int n_in,
                              void* d_out, int out_size) {
    const float* Xt = (const float*)d_in[0];   // (m, 128)
    const float* X  = (const float*)d_in[1];   // (n, 128)
    const float* w  = (const float*)d_in[2];   // (n,)

    const int m = in_sizes[0] / D;
    const int n = in_sizes[2];

    const int tiles_per_chunk = (n + NCHUNK * NT - 1) / (NCHUNK * NT);   // 22
    const int chunksz = tiles_per_chunk * NT;                            // 2816
    const int n_pad = NCHUNK * chunksz;                                  // 104192
    const int n_items = (m / MB) * NCHUNK;                               // 592

    cudaFuncSetAttribute(k_main, cudaFuncAttributeMaxDynamicSharedMemorySize, SMEM_TOTAL);

    k_prepx<<<(n_pad + 255) / 256, 256>>>(X, w, n, n_pad);
    k_prepq<<<(m + 127) / 128, 128>>>(Xt, m);
    k_dummy<<<1, 32>>>();
    k_main<<<GRID_MAIN, NTHREADS, SMEM_TOTAL>>>(n, n_items, chunksz);   // 4th launch -> ncu
    k_select<<<(m + 7) / 8, 256>>>(Xt, X, w, (float*)d_out, m);
}

// round 9
// speedup vs baseline: 3.9163x; 1.0642x over previous
// bf16 screen (2 CTA/SM, x2-seeded acc, mma.sync) + warp-select + exact rescore
#include <cuda_runtime.h>
#include <cuda_bf16.h>
#include <cfloat>
#include <cstdint>

#define D        128
#define MB       64           // queries per block tile
#define NT       128          // x-points per inner tile
#define KSEL     10
#define NCHUNK   37
#define GRID_MAIN 296         // 2 CTAs per SM * 148
#define NTHREADS 256
#define MAX_NP   104192       // 37 * 22 * 128
#define MAX_M    2048
#define LCELL    3            // top-L per (thread, row) cell
#define KCH      24           // 8 cells * LCELL per (query, chunk)
#define NCAND    (NCHUNK * KCH)   // 888

// smem layout (bytes)
#define ROWPITCH 272                        // 136 bf16 per row (128 data + pad)
#define SQ_OFF   0                          // 64 rows * 272 = 17408
#define SX_OFF   (MB * ROWPITCH)            // 17408
#define SX_SLOT  (128 * ROWPITCH)           // 34816 per slot, 2 slots
#define SX2_OFF  (SX_OFF + 2 * SX_SLOT)     // 87040
#define SMEM_TOTAL (SX2_OFF + 2 * NT * 4)   // 88064

__device__ float g_x2a[MAX_NP];              // ||x||^2 - w  (ranking-equivalent)
__device__ uint4 g_xh[MAX_NP * 16];          // X hi bf16, row = 16 x uint4 (256B)
__device__ uint4 g_qh[MAX_M * 16];           // Q scaled by -2, bf16
__device__ float g_cand_r[MAX_M * NCAND];
__device__ int   g_cand_j[MAX_M * NCAND];
__device__ int   g_dummy;

// ---------------------------------------------------------------- helpers
__device__ __forceinline__ uint32_t smem_u32(const void* p) {
    uint32_t a;
    asm("{ .reg .u64 t; cvta.to.shared.u64 t, %1; cvt.u32.u64 %0, t; }" : "=r"(a) : "l"(p));
    return a;
}
__device__ __forceinline__ void cp_async16(uint32_t dst, const void* src) {
    asm volatile("cp.async.ca.shared.global [%0], [%1], 16;" :: "r"(dst), "l"(src));
}
#define CP_COMMIT() asm volatile("cp.async.commit_group;" ::: "memory")
#define CP_WAIT0()  asm volatile("cp.async.wait_group 0;" ::: "memory")

__device__ __forceinline__ void ldm_x4(uint32_t& r0, uint32_t& r1, uint32_t& r2, uint32_t& r3,
                                       uint32_t addr) {
    asm volatile("ldmatrix.sync.aligned.m8n8.x4.shared.b16 {%0,%1,%2,%3}, [%4];"
                 : "=r"(r0), "=r"(r1), "=r"(r2), "=r"(r3) : "r"(addr));
}
__device__ __forceinline__ void mma_bf16(float* c, const uint32_t* a, const uint32_t* b) {
    asm volatile("mma.sync.aligned.m16n8k16.row.col.f32.bf16.bf16.f32 "
                 "{%0,%1,%2,%3}, {%4,%5,%6,%7}, {%8,%9}, {%0,%1,%2,%3};"
                 : "+f"(c[0]), "+f"(c[1]), "+f"(c[2]), "+f"(c[3])
                 : "r"(a[0]), "r"(a[1]), "r"(a[2]), "r"(a[3]), "r"(b[0]), "r"(b[1]));
}

template <int KK>
__device__ __forceinline__ void topk_insert(float r, int j, float* br, int* bj) {
#pragma unroll
    for (int t = 0; t < KK; t++) {
        if (r < br[t]) {
            float tr = br[t]; int tj = bj[t];
            br[t] = r; bj[t] = j; r = tr; j = tj;
        }
    }
}

// ---------------------------------------------------------------- prep
__global__ void k_prepx(const float* __restrict__ X, const float* __restrict__ w,
                        int n, int n_pad) {
    int j = blockIdx.x * blockDim.x + threadIdx.x;
    if (j >= n_pad) return;
    if (j >= n) {
        uint4 z = make_uint4(0, 0, 0, 0);
#pragma unroll
        for (int g = 0; g < 16; g++) g_xh[(size_t)j * 16 + g] = z;
        g_x2a[j] = 1e30f;
        return;
    }
    const float4* row = (const float4*)(X + (size_t)j * D);
    float x2 = 0.f;
#pragma unroll
    for (int g = 0; g < 16; g++) {
        float4 f0 = row[2 * g], f1 = row[2 * g + 1];
        x2 += f0.x * f0.x + f0.y * f0.y + f0.z * f0.z + f0.w * f0.w;
        x2 += f1.x * f1.x + f1.y * f1.y + f1.z * f1.z + f1.w * f1.w;
        __nv_bfloat162 h0 = __floats2bfloat162_rn(f0.x, f0.y);
        __nv_bfloat162 h1 = __floats2bfloat162_rn(f0.z, f0.w);
        __nv_bfloat162 h2 = __floats2bfloat162_rn(f1.x, f1.y);
        __nv_bfloat162 h3 = __floats2bfloat162_rn(f1.z, f1.w);
        uint4 h;
        h.x = *reinterpret_cast<uint32_t*>(&h0);
        h.y = *reinterpret_cast<uint32_t*>(&h1);
        h.z = *reinterpret_cast<uint32_t*>(&h2);
        h.w = *reinterpret_cast<uint32_t*>(&h3);
        g_xh[(size_t)j * 16 + g] = h;
    }
    g_x2a[j] = x2 - w[j];   // additive wmax const dropped: ranking-invariant
}

// Q pre-scaled by -2 (exact in bf16): dot accumulates -2*q.x directly
__global__ void k_prepq(const float* __restrict__ Xt, int m) {
    int i = blockIdx.x * blockDim.x + threadIdx.x;
    if (i >= m) return;
    const float4* row = (const float4*)(Xt + (size_t)i * D);
#pragma unroll
    for (int g = 0; g < 16; g++) {
        float4 f0 = row[2 * g], f1 = row[2 * g + 1];
        __nv_bfloat162 h0 = __floats2bfloat162_rn(-2.f * f0.x, -2.f * f0.y);
        __nv_bfloat162 h1 = __floats2bfloat162_rn(-2.f * f0.z, -2.f * f0.w);
        __nv_bfloat162 h2 = __floats2bfloat162_rn(-2.f * f1.x, -2.f * f1.y);
        __nv_bfloat162 h3 = __floats2bfloat162_rn(-2.f * f1.z, -2.f * f1.w);
        uint4 h;
        h.x = *reinterpret_cast<uint32_t*>(&h0);
        h.y = *reinterpret_cast<uint32_t*>(&h1);
        h.z = *reinterpret_cast<uint32_t*>(&h2);
        h.w = *reinterpret_cast<uint32_t*>(&h3);
        g_qh[(size_t)i * 16 + g] = h;
    }
}

__global__ void k_dummy() { if (threadIdx.x == 0) g_dummy = 1; }

// ---------------------------------------------------------------- main screen
__device__ __forceinline__ void load_x(uint32_t sbase, int slot, int jt, int tid) {
#pragma unroll
    for (int e = tid; e < 2048; e += NTHREADS) {       // 8 iters: 128 rows x 16 u4
        int r = e >> 4, c = e & 15;
        cp_async16(sbase + SX_OFF + slot * SX_SLOT + r * ROWPITCH + c * 16,
                   g_xh + ((size_t)(jt + r) * 16 + c));
    }
    if (tid < 32)
        cp_async16(sbase + SX2_OFF + slot * 512 + tid * 16, g_x2a + jt + tid * 4);
}

__global__ void __launch_bounds__(NTHREADS, 2)
k_main(int n, int n_items, int chunksz) {
    extern __shared__ char smem[];
    float* sx2 = (float*)(smem + SX2_OFF);
    const uint32_t sbase = smem_u32(smem);
    const int tid = threadIdx.x;
    const int lane = tid & 31;
    const int wid = tid >> 5;
    const int wm = wid >> 1;     // 0..3 -> 16-row strip
    const int wn = wid & 1;      // 0..1 -> 64-col half

    const int a_row  = (lane & 15);
    const int a_colb = ((lane >> 4) * 8) * 2;
    const int b_row  = ((lane >> 4) << 3) + (lane & 7);
    const int b_colb = (((lane >> 3) & 1) * 8) * 2;
    const int cbase  = wn * 64 + (lane & 3) * 2;   // this thread's first column

    const int tiles_full = chunksz / NT;

    for (int it = blockIdx.x; it < n_items; it += gridDim.x) {
        const int qtile = it / NCHUNK;
        const int chunk = it - qtile * NCHUNK;
        const int j0 = chunk * chunksz;
        int T = tiles_full;
        {
            int rem = n - j0;
            int tr = (rem > 0) ? (rem + NT - 1) / NT : 0;
            if (tr < T) T = tr;
        }

        float br0[LCELL], br1[LCELL]; int bj0[LCELL], bj1[LCELL];
#pragma unroll
        for (int t = 0; t < LCELL; t++) {
            br0[t] = FLT_MAX; bj0[t] = -1;
            br1[t] = FLT_MAX; bj1[t] = -1;
        }

        if (T > 0) {
            // Q tile: 64 rows x 16 u4
#pragma unroll
            for (int e = tid; e < MB * 16; e += NTHREADS) {
                int r = e >> 4, c = e & 15;
                cp_async16(sbase + SQ_OFF + r * ROWPITCH + c * 16,
                           g_qh + ((size_t)(qtile * MB + r) * 16 + c));
            }
            CP_COMMIT();
            load_x(sbase, 0, j0, tid);
            CP_COMMIT();

            for (int t = 0; t < T; t++) {
                const int cur = t & 1;
                CP_WAIT0();
                __syncthreads();
                if (t + 1 < T) { load_x(sbase, 1 - cur, j0 + (t + 1) * NT, tid); CP_COMMIT(); }

                const float* x2s = sx2 + cur * NT;

                // seed accumulators with x2a -> after k-loop acc == x2a - 2 q.x
                float acc[8][4];
#pragma unroll
                for (int nf8 = 0; nf8 < 8; nf8++) {
                    const int c = cbase + nf8 * 8;
                    const float x0 = x2s[c], x1 = x2s[c + 1];
                    acc[nf8][0] = x0; acc[nf8][1] = x1;
                    acc[nf8][2] = x0; acc[nf8][3] = x1;
                }

                const uint32_t abase0 = sbase + SQ_OFF + (wm * 16 + a_row) * ROWPITCH + a_colb;
                const uint32_t bbase0 = sbase + SX_OFF + cur * SX_SLOT
                                      + (wn * 64 + b_row) * ROWPITCH + b_colb;
#pragma unroll
                for (int ks = 0; ks < 8; ks++) {
                    const uint32_t kb = ks * 32;
                    uint32_t a[4], b[4][4];
                    ldm_x4(a[0], a[1], a[2], a[3], abase0 + kb);
#pragma unroll
                    for (int nf = 0; nf < 4; nf++)
                        ldm_x4(b[nf][0], b[nf][1], b[nf][2], b[nf][3],
                               bbase0 + nf * 16 * ROWPITCH + kb);
#pragma unroll
                    for (int nf = 0; nf < 4; nf++) {
                        mma_bf16(acc[2 * nf],     a, &b[nf][0]);
                        mma_bf16(acc[2 * nf + 1], a, &b[nf][2]);
                    }
                }

                // compare-only epilogue
                const int jb = j0 + t * NT;
                float thr0 = br0[LCELL - 1], thr1 = br1[LCELL - 1];
#pragma unroll
                for (int nf8 = 0; nf8 < 8; nf8++) {
                    const int c = cbase + nf8 * 8;
                    if (acc[nf8][0] < thr0) { topk_insert<LCELL>(acc[nf8][0], jb + c,     br0, bj0); thr0 = br0[LCELL - 1]; }
                    if (acc[nf8][1] < thr0) { topk_insert<LCELL>(acc[nf8][1], jb + c + 1, br0, bj0); thr0 = br0[LCELL - 1]; }
                    if (acc[nf8][2] < thr1) { topk_insert<LCELL>(acc[nf8][2], jb + c,     br1, bj1); thr1 = br1[LCELL - 1]; }
                    if (acc[nf8][3] < thr1) { topk_insert<LCELL>(acc[nf8][3], jb + c + 1, br1, bj1); thr1 = br1[LCELL - 1]; }
                }
            }
        }

        // write this thread's cells (rows wm*16+(lane>>2) and +8)
        {
            const int q0 = qtile * MB + wm * 16 + (lane >> 2);
            const int cell = wn * 4 + (lane & 3);      // 0..7
            size_t b0 = (size_t)q0 * NCAND + chunk * KCH + cell * LCELL;
            size_t b1 = (size_t)(q0 + 8) * NCAND + chunk * KCH + cell * LCELL;
#pragma unroll
            for (int t = 0; t < LCELL; t++) {
                g_cand_r[b0 + t] = br0[t];  g_cand_j[b0 + t] = bj0[t];
                g_cand_r[b1 + t] = br1[t];  g_cand_j[b1 + t] = bj1[t];
            }
        }
        __syncthreads();   // smem safe before next item's loads
    }
}

// ------------------------------------------- warp-per-query select + rescore
__global__ void k_select(const float* __restrict__ Xt, const float* __restrict__ X,
                         const float* __restrict__ w, float* __restrict__ out, int m) {
    __shared__ float sq[8][D];
    const int lane = threadIdx.x & 31;
    const int wgrp = threadIdx.x >> 5;
    const int q = blockIdx.x * 8 + wgrp;
    if (q >= m) return;

#pragma unroll
    for (int e = lane; e < D; e += 32) sq[wgrp][e] = Xt[(size_t)q * D + e];
    __syncwarp();

    // per-lane top-8 over candidates (stride-32, coalesced)
    float lr[8]; int lj[8];
#pragma unroll
    for (int t = 0; t < 8; t++) { lr[t] = FLT_MAX; lj[t] = -1; }
    const size_t base = (size_t)q * NCAND;
    for (int c = lane; c < NCAND; c += 32) {
        float r = g_cand_r[base + c];
        if (r < lr[7] && r < 1e29f) {
            int j = g_cand_j[base + c];
            if (j >= 0) topk_insert<8>(r, j, lr, lj);
        }
    }

    // 32-round warp argmin pop -> top-32 of the union
    int myj = -1;
    int p = 0;
    for (int round = 0; round < 32; round++) {
        float v = (p < 8) ? lr[p] : FLT_MAX;
        float bv = v; int bl = lane;
#pragma unroll
        for (int o = 16; o > 0; o >>= 1) {
            float ov = __shfl_xor_sync(0xffffffffu, bv, o);
            int   ol = __shfl_xor_sync(0xffffffffu, bl, o);
            if (ov < bv || (ov == bv && ol < bl)) { bv = ov; bl = ol; }
        }
        int jcur = (p < 8) ? lj[p] : -1;
        int jpop = __shfl_sync(0xffffffffu, jcur, bl);
        if (lane == round && bv < 1e29f) myj = jpop;
        if (lane == bl) p++;
    }

    // exact fp32 rescore
    float s = FLT_MAX, act = -FLT_MAX;
    if (myj >= 0) {
        const float4* xr = (const float4*)(X + (size_t)myj * D);
        const float4* qr = (const float4*)(sq[wgrp]);
        float d2 = 0.f;
#pragma unroll
        for (int v = 0; v < 32; v++) {
            float4 x = xr[v], qq = qr[v];
            float dx = x.x - qq.x, dy = x.y - qq.y, dz = x.z - qq.z, dw = x.w - qq.w;
            d2 += dx * dx + dy * dy + dz * dz + dw * dw;
        }
        float wj = w[myj];
        s = d2 - wj;              // exact augmented key (wmax const dropped)
        act = wj - sqrtf(d2);     // K_CONST = 1
    }

    // exact top-10 by s, max act over them
    float mx = -FLT_MAX;
    for (int round = 0; round < KSEL; round++) {
        float bv = s; int bl = lane;
#pragma unroll
        for (int o = 16; o > 0; o >>= 1) {
            float ov = __shfl_xor_sync(0xffffffffu, bv, o);
            int   ol = __shfl_xor_sync(0xffffffffu, bl, o);
            if (ov < bv || (ov == bv && ol < bl)) { bv = ov; bl = ol; }
        }
        float awin = __shfl_sync(0xffffffffu, act, bl);
        if (bv < FLT_MAX) mx = fmaxf(mx, awin);
        if (lane == bl) s = FLT_MAX;
    }
    if (lane == 0) out[q] = mx;
}

// ---------------------------------------------------------------- launch
extern "C" void kernel_launch(void* const* d_in, const int* in_sizes, int n_in,
                              void* d_out, int out_size) {
    const float* Xt = (const float*)d_in[0];   // (m, 128)
    const float* X  = (const float*)d_in[1];   // (n, 128)
    const float* w  = (const float*)d_in[2];   // (n,)

    const int m = in_sizes[0] / D;
    const int n = in_sizes[2];

    const int tiles_per_chunk = (n + NCHUNK * NT - 1) / (NCHUNK * NT);   // 22
    const int chunksz = tiles_per_chunk * NT;                            // 2816
    const int n_pad = NCHUNK * chunksz;                                  // 104192
    const int n_items = (m / MB) * NCHUNK;                               // 1184

    cudaFuncSetAttribute(k_main, cudaFuncAttributeMaxDynamicSharedMemorySize, SMEM_TOTAL);

    k_prepx<<<(n_pad + 255) / 256, 256>>>(X, w, n, n_pad);
    k_prepq<<<(m + 127) / 128, 128>>>(Xt, m);
    k_dummy<<<1, 32>>>();
    k_main<<<GRID_MAIN, NTHREADS, SMEM_TOTAL>>>(n, n_items, chunksz);   // 4th launch -> ncu
    k_select<<<(m + 7) / 8, 256>>>(Xt, X, w, (float*)d_out, m);
}